// round 1
// baseline (speedup 1.0000x reference)
#include <cuda_runtime.h>
#include <math.h>

#define N_NODES   20000
#define N_EDGES   320000
#define NODE_DIM  512
#define HIDDEN    512
#define N_GRAPHS  64
#define HALF_H    (HIDDEN/2)

// ---------------- device scratch (no allocations allowed) ----------------
__device__ float g_y[N_NODES * NODE_DIM];      // (I+A) x
__device__ float g_z[N_NODES * NODE_DIM];      // (I+A)^2 x
__device__ int   g_deg[N_NODES];               // in-degree
__device__ int   g_rowstart[N_NODES + 1];      // CSR row offsets (by dst)
__device__ int   g_cursor[N_NODES];            // scatter cursors
__device__ int   g_csrsrc[N_EDGES];            // src per CSR slot
__device__ int   g_gstart[N_GRAPHS + 1];       // per-graph node ranges
__device__ float g_q[N_GRAPHS * HIDDEN];       // pooled (I+A)^2 x
__device__ float g_d1[N_GRAPHS];               // pooled (1 + indeg)
__device__ float g_cnt[N_GRAPHS];              // nodes per graph
__device__ float g_t[N_GRAPHS * HIDDEN];
__device__ float g_pooled[N_GRAPHS * HIDDEN];
__device__ float g_zc[N_GRAPHS * HALF_H];

// ---------------- kernels ----------------

__global__ void k_zero_deg() {
    int i = blockIdx.x * blockDim.x + threadIdx.x;
    if (i < N_NODES) g_deg[i] = 0;
}

// graph boundaries from sorted batch: gstart[g] = first i with batch[i] >= g
__global__ void k_graph_bounds(const int* __restrict__ batch) {
    int i = blockIdx.x * blockDim.x + threadIdx.x;
    if (i >= N_NODES) return;
    int b  = batch[i];
    int bp = (i == 0) ? -1 : batch[i - 1];
    for (int g = bp + 1; g <= b; ++g) g_gstart[g] = i;
    if (i == N_NODES - 1)
        for (int g = b + 1; g <= N_GRAPHS; ++g) g_gstart[g] = N_NODES;
}

__global__ void k_hist(const int* __restrict__ dst) {
    int e = blockIdx.x * blockDim.x + threadIdx.x;
    if (e < N_EDGES) atomicAdd(&g_deg[dst[e]], 1);
}

// single-block exclusive scan of g_deg -> g_rowstart / g_cursor
__global__ void k_scan() {
    __shared__ int sm[1024];
    const int CH = 20;                       // 1024*20 = 20480 >= 20000
    int t = threadIdx.x;
    int base = t * CH;
    int loc[CH];
    int s = 0;
    #pragma unroll
    for (int i = 0; i < CH; ++i) {
        int idx = base + i;
        int v = (idx < N_NODES) ? g_deg[idx] : 0;
        loc[i] = s;
        s += v;
    }
    sm[t] = s;
    __syncthreads();
    for (int off = 1; off < 1024; off <<= 1) {
        int v = (t >= off) ? sm[t - off] : 0;
        __syncthreads();
        sm[t] += v;
        __syncthreads();
    }
    int pre = (t > 0) ? sm[t - 1] : 0;
    #pragma unroll
    for (int i = 0; i < CH; ++i) {
        int idx = base + i;
        if (idx < N_NODES) {
            int v = pre + loc[i];
            g_rowstart[idx] = v;
            g_cursor[idx]   = v;
        }
    }
    if (t == 1023) g_rowstart[N_NODES] = sm[1023];
}

__global__ void k_scatter(const int* __restrict__ src, const int* __restrict__ dst) {
    int e = blockIdx.x * blockDim.x + threadIdx.x;
    if (e < N_EDGES) {
        int p = atomicAdd(&g_cursor[dst[e]], 1);
        g_csrsrc[p] = src[e];
    }
}

// sort each node's src segment -> deterministic summation order across runs
__global__ void k_sortseg() {
    int i = blockIdx.x * blockDim.x + threadIdx.x;
    if (i >= N_NODES) return;
    int b = g_rowstart[i], e = g_rowstart[i + 1];
    for (int j = b + 1; j < e; ++j) {
        int key = g_csrsrc[j];
        int k = j - 1;
        while (k >= b && g_csrsrc[k] > key) { g_csrsrc[k + 1] = g_csrsrc[k]; --k; }
        g_csrsrc[k + 1] = key;
    }
}

// out[i] = in[i] + sum_{j in-neighbors(i)} in[j]   (one block per node, float4 lanes)
__global__ void __launch_bounds__(128) k_agg(const float* __restrict__ in,
                                             float* __restrict__ out) {
    __shared__ int s_src[128];
    int node = blockIdx.x;
    int tid  = threadIdx.x;
    const float4* iv = (const float4*)in;
    int beg = g_rowstart[node], end = g_rowstart[node + 1];
    float4 acc = iv[node * 128 + tid];
    for (int tb = beg; tb < end; tb += 128) {
        int n = min(128, end - tb);
        if (tid < n) s_src[tid] = g_csrsrc[tb + tid];
        __syncthreads();
        int e = 0;
        for (; e + 4 <= n; e += 4) {
            int s0 = s_src[e], s1 = s_src[e + 1], s2 = s_src[e + 2], s3 = s_src[e + 3];
            float4 a = iv[s0 * 128 + tid];
            float4 b = iv[s1 * 128 + tid];
            float4 c = iv[s2 * 128 + tid];
            float4 d = iv[s3 * 128 + tid];
            acc.x += a.x + b.x + c.x + d.x;
            acc.y += a.y + b.y + c.y + d.y;
            acc.z += a.z + b.z + c.z + d.z;
            acc.w += a.w + b.w + c.w + d.w;
        }
        for (; e < n; ++e) {
            float4 a = iv[s_src[e] * 128 + tid];
            acc.x += a.x; acc.y += a.y; acc.z += a.z; acc.w += a.w;
        }
        __syncthreads();
    }
    ((float4*)out)[node * 128 + tid] = acc;
}

// per-graph pooling of g_z, plus d1 = sum(1+deg), cnt = #nodes
__global__ void __launch_bounds__(128) k_pool() {
    int g = blockIdx.x, tid = threadIdx.x;
    int beg = g_gstart[g], end = g_gstart[g + 1];
    const float4* zv = (const float4*)g_z;
    float4 acc = make_float4(0.f, 0.f, 0.f, 0.f);
    float dsum = 0.f;
    for (int n = beg; n < end; ++n) {
        float4 v = zv[n * 128 + tid];
        acc.x += v.x; acc.y += v.y; acc.z += v.z; acc.w += v.w;
        if (tid == 0) dsum += 1.f + (float)g_deg[n];
    }
    ((float4*)g_q)[g * 128 + tid] = acc;
    if (tid == 0) { g_d1[g] = dsum; g_cnt[g] = (float)(end - beg); }
}

// out[g, tid] = dot(in_row, W[:, tid]) + scale[g] * bias[tid]   (W row-major [512,512])
__global__ void __launch_bounds__(512) k_gemm512(const float* __restrict__ in,
                                                 const float* __restrict__ W,
                                                 const float* __restrict__ bias,
                                                 const float* __restrict__ scale,
                                                 float* __restrict__ out) {
    __shared__ float qs[HIDDEN];
    int g = blockIdx.x, tid = threadIdx.x;
    qs[tid] = in[g * HIDDEN + tid];
    __syncthreads();
    float a0 = 0.f, a1 = 0.f, a2 = 0.f, a3 = 0.f;
    #pragma unroll 4
    for (int k = 0; k < HIDDEN; k += 4) {
        a0 += qs[k]     * W[(k)     * HIDDEN + tid];
        a1 += qs[k + 1] * W[(k + 1) * HIDDEN + tid];
        a2 += qs[k + 2] * W[(k + 2) * HIDDEN + tid];
        a3 += qs[k + 3] * W[(k + 3) * HIDDEN + tid];
    }
    out[g * HIDDEN + tid] = (a0 + a1) + (a2 + a3) + scale[g] * bias[tid];
}

// zc = relu(pooled @ W_c1 + b_c1), W_c1 row-major [512, 256]
__global__ void __launch_bounds__(256) k_gemm_c1(const float* __restrict__ W,
                                                 const float* __restrict__ bias) {
    __shared__ float ps[HIDDEN];
    int g = blockIdx.x, tid = threadIdx.x;
    ps[tid]       = g_pooled[g * HIDDEN + tid];
    ps[tid + 256] = g_pooled[g * HIDDEN + tid + 256];
    __syncthreads();
    float a0 = 0.f, a1 = 0.f, a2 = 0.f, a3 = 0.f;
    #pragma unroll 4
    for (int k = 0; k < HIDDEN; k += 4) {
        a0 += ps[k]     * W[(k)     * HALF_H + tid];
        a1 += ps[k + 1] * W[(k + 1) * HALF_H + tid];
        a2 += ps[k + 2] * W[(k + 2) * HALF_H + tid];
        a3 += ps[k + 3] * W[(k + 3) * HALF_H + tid];
    }
    float v = (a0 + a1) + (a2 + a3) + bias[tid];
    g_zc[g * HALF_H + tid] = v > 0.f ? v : 0.f;
}

// score + sigmoid
__global__ void __launch_bounds__(256) k_final(const float* __restrict__ Wc2,
                                               const float* __restrict__ bc2,
                                               float* __restrict__ out) {
    __shared__ float red[256];
    int g = blockIdx.x, tid = threadIdx.x;
    red[tid] = g_zc[g * HALF_H + tid] * Wc2[tid];
    __syncthreads();
    for (int s = 128; s > 0; s >>= 1) {
        if (tid < s) red[tid] += red[tid + s];
        __syncthreads();
    }
    if (tid == 0) {
        float sc = red[0] + bc2[0];
        out[g] = 1.f / (1.f + expf(-sc));
    }
}

// ---------------- host launch ----------------
extern "C" void kernel_launch(void* const* d_in, const int* in_sizes, int n_in,
                              void* d_out, int out_size) {
    const float* x     = (const float*)d_in[0];
    const int*   eidx  = (const int*)  d_in[1];
    const int*   batch = (const int*)  d_in[2];
    const float* W_g1  = (const float*)d_in[3];
    const float* b_g1  = (const float*)d_in[4];
    const float* W_g2  = (const float*)d_in[5];
    const float* b_g2  = (const float*)d_in[6];
    const float* W_c1  = (const float*)d_in[7];
    const float* b_c1  = (const float*)d_in[8];
    const float* W_c2  = (const float*)d_in[9];
    const float* b_c2  = (const float*)d_in[10];
    float* out = (float*)d_out;

    const int* src = eidx;
    const int* dst = eidx + N_EDGES;

    float *y_ptr, *z_ptr, *q_ptr, *d1_ptr, *cnt_ptr, *t_ptr, *pooled_ptr;
    cudaGetSymbolAddress((void**)&y_ptr,  g_y);
    cudaGetSymbolAddress((void**)&z_ptr,  g_z);
    cudaGetSymbolAddress((void**)&q_ptr,  g_q);
    cudaGetSymbolAddress((void**)&d1_ptr, g_d1);
    cudaGetSymbolAddress((void**)&cnt_ptr,g_cnt);
    cudaGetSymbolAddress((void**)&t_ptr,  g_t);
    cudaGetSymbolAddress((void**)&pooled_ptr, g_pooled);

    k_zero_deg<<<(N_NODES + 511) / 512, 512>>>();
    k_graph_bounds<<<(N_NODES + 255) / 256, 256>>>(batch);
    k_hist<<<N_EDGES / 512, 512>>>(dst);
    k_scan<<<1, 1024>>>();
    k_scatter<<<N_EDGES / 512, 512>>>(src, dst);
    k_sortseg<<<(N_NODES + 255) / 256, 256>>>();
    k_agg<<<N_NODES, 128>>>(x, y_ptr);
    k_agg<<<N_NODES, 128>>>(y_ptr, z_ptr);
    k_pool<<<N_GRAPHS, 128>>>();
    k_gemm512<<<N_GRAPHS, 512>>>(q_ptr, W_g1, b_g1, d1_ptr, t_ptr);
    k_gemm512<<<N_GRAPHS, 512>>>(t_ptr, W_g2, b_g2, cnt_ptr, pooled_ptr);
    k_gemm_c1<<<N_GRAPHS, 256>>>(W_c1, b_c1);
    k_final<<<N_GRAPHS, 256>>>(W_c2, b_c2, out);
}

// round 2
// speedup vs baseline: 1.8084x; 1.8084x over previous
#include <cuda_runtime.h>
#include <math.h>

#define N_NODES   20000
#define N_EDGES   320000
#define HIDDEN    512
#define N_GRAPHS  64
#define HALF_H    256
#define NCHUNK    150
#define CHS       134      // 150*134 = 20100 >= 20000

// ---------------- device scratch ----------------
__device__ __align__(16) int   g_deg[N_NODES];          // out-degree (by src, for CSR)
__device__ __align__(16) int   g_indeg[N_NODES];        // in-degree (for d1)
__device__ __align__(16) int   g_rowstart[N_NODES + 4];
__device__ __align__(16) int   g_cursor[N_NODES];
__device__ __align__(16) int   g_csrdst[N_EDGES];
__device__           int       g_gstart[N_GRAPHS + 1];
__device__ __align__(16) unsigned short g_w1[N_NODES * 32];   // u8 counts, 2 per u16
__device__ __align__(16) float g_w2[N_NODES * 64];
__device__ __align__(16) float g_part[NCHUNK * HIDDEN * N_GRAPHS]; // 19.7MB partials
__device__ __align__(16) float g_q[N_GRAPHS * HIDDEN];
__device__           float     g_d1[N_GRAPHS];
__device__           float     g_cnt[N_GRAPHS];
__device__ __align__(16) float g_t[N_GRAPHS * HIDDEN];
__device__ __align__(16) float g_pooled[N_GRAPHS * HIDDEN];

// ---------------- f32x2 helpers ----------------
#define FFMA2(acc, a, b) \
    asm("fma.rn.f32x2 %0, %1, %2, %3;" : "=l"(acc) : "l"(a), "l"(b), "l"(acc))
#define PACKDUP(out, fu) \
    asm("mov.b64 %0, {%1, %1};" : "=l"(out) : "r"(fu))

// ---------------- kernels ----------------

__global__ void k_init(const int* __restrict__ batch) {
    int i = blockIdx.x * blockDim.x + threadIdx.x;
    if (i >= N_NODES) return;
    g_deg[i] = 0;
    g_indeg[i] = 0;
    int b  = batch[i];
    int bp = (i == 0) ? -1 : batch[i - 1];
    for (int g = bp + 1; g <= b; ++g) g_gstart[g] = i;
    if (i == N_NODES - 1)
        for (int g = b + 1; g <= N_GRAPHS; ++g) g_gstart[g] = N_NODES;
}

__global__ void k_hist(const int* __restrict__ src, const int* __restrict__ dst) {
    int e = blockIdx.x * blockDim.x + threadIdx.x;
    if (e < N_EDGES) {
        atomicAdd(&g_deg[src[e]], 1);
        atomicAdd(&g_indeg[dst[e]], 1);
    }
}

// exclusive scan of g_deg -> rowstart / cursor  (int4 everywhere)
__global__ void k_scan() {
    __shared__ int sm[1024];
    int t = threadIdx.x;
    int base = t * 20;                 // N_NODES = 20000 = 1000*20
    bool act = base < N_NODES;
    int4 v[5];
    int s = 0;
    if (act) {
        const int4* dv = (const int4*)g_deg;
        #pragma unroll
        for (int i = 0; i < 5; ++i) {
            v[i] = dv[base / 4 + i];
            s += v[i].x + v[i].y + v[i].z + v[i].w;
        }
    }
    sm[t] = s;
    __syncthreads();
    for (int off = 1; off < 1024; off <<= 1) {
        int u = (t >= off) ? sm[t - off] : 0;
        __syncthreads();
        sm[t] += u;
        __syncthreads();
    }
    int pre = (t > 0) ? sm[t - 1] : 0;
    if (act) {
        int run = pre;
        int4* rs = (int4*)g_rowstart;
        int4* cu = (int4*)g_cursor;
        #pragma unroll
        for (int i = 0; i < 5; ++i) {
            int4 o;
            o.x = run; run += v[i].x;
            o.y = run; run += v[i].y;
            o.z = run; run += v[i].z;
            o.w = run; run += v[i].w;
            rs[base / 4 + i] = o;
            cu[base / 4 + i] = o;
        }
        if (t == 999) g_rowstart[N_NODES] = run;
    }
}

__global__ void k_scatter(const int* __restrict__ src, const int* __restrict__ dst) {
    int e = blockIdx.x * blockDim.x + threadIdx.x;
    if (e < N_EDGES) {
        int p = atomicAdd(&g_cursor[src[e]], 1);
        g_csrdst[p] = dst[e];
    }
}

// w1 = (I+A^T)P : per-node counts of neighbor graphs, u8 packed (warp per node)
__global__ void __launch_bounds__(256) k_w1(const int* __restrict__ batch) {
    int wid = threadIdx.x >> 5, l = threadIdx.x & 31;
    int n = blockIdx.x * 8 + wid;
    if (n >= N_NODES) return;
    int beg = g_rowstart[n], end = g_rowstart[n + 1];
    int bn = batch[n];
    int c0 = (bn == 2 * l), c1 = (bn == 2 * l + 1);
    for (int base = beg; base < end; base += 32) {
        int e = base + l;
        int b = -1;
        if (e < end) b = batch[g_csrdst[e]];
        int m = min(32, end - base);
        for (int k = 0; k < m; ++k) {
            int bk = __shfl_sync(0xffffffffu, b, k);
            c0 += (bk == 2 * l);
            c1 += (bk == 2 * l + 1);
        }
    }
    g_w1[n * 32 + l] = (unsigned short)(c0 | (c1 << 8));
}

// w2 = (I+A^T)w1, float output (warp per node, u16 gathers)
__global__ void __launch_bounds__(256) k_w2() {
    int wid = threadIdx.x >> 5, l = threadIdx.x & 31;
    int n = blockIdx.x * 8 + wid;
    if (n >= N_NODES) return;
    int beg = g_rowstart[n], end = g_rowstart[n + 1];
    unsigned v = g_w1[n * 32 + l];
    int a0 = v & 0xff, a1 = v >> 8;
    for (int base = beg; base < end; base += 32) {
        int e = base + l;
        int d = 0;
        if (e < end) d = g_csrdst[e];
        int m = min(32, end - base);
        #pragma unroll 4
        for (int k = 0; k < m; ++k) {
            int dk = __shfl_sync(0xffffffffu, d, k);
            unsigned u = g_w1[dk * 32 + l];
            a0 += u & 0xff;
            a1 += u >> 8;
        }
    }
    float2 o = make_float2((float)a0, (float)a1);
    *(float2*)&g_w2[n * 64 + 2 * l] = o;
}

// q partials: block = (node chunk c, dim tile dt). tile 256 dims x 64 graphs.
// thread: 8 dims (4 f32x2 pairs) x 8 graphs, packed fma.rn.f32x2
__global__ void __launch_bounds__(256) k_qgemm(const float* __restrict__ x) {
    int c  = blockIdx.x;          // 0..NCHUNK-1
    int dt = blockIdx.y;          // 0..1
    int t  = threadIdx.x;
    int tg = t & 7;               // graphs 8*tg..+7
    int td = t >> 3;              // dims d0+8*td..+7
    int d0 = dt * 256;

    unsigned long long acc[4][8];
    #pragma unroll
    for (int p = 0; p < 4; ++p)
        #pragma unroll
        for (int g = 0; g < 8; ++g) acc[p][g] = 0ull;

    int i0 = c * CHS;
    int i1 = min(i0 + CHS, N_NODES);
    const double2* xd = (const double2*)x;          // 128 double2 per row
    const float4*  wv = (const float4*)g_w2;        // 16 float4 per row
    int xbase = d0 / 4 + 2 * td;

    for (int i = i0; i < i1; ++i) {
        double2 xa = xd[i * 128 + xbase];
        double2 xb = xd[i * 128 + xbase + 1];
        float4  wa = wv[i * 16 + 2 * tg];
        float4  wb = wv[i * 16 + 2 * tg + 1];
        unsigned long long xp[4];
        xp[0] = __double_as_longlong(xa.x);
        xp[1] = __double_as_longlong(xa.y);
        xp[2] = __double_as_longlong(xb.x);
        xp[3] = __double_as_longlong(xb.y);
        unsigned long long wd_[8];
        PACKDUP(wd_[0], __float_as_uint(wa.x));
        PACKDUP(wd_[1], __float_as_uint(wa.y));
        PACKDUP(wd_[2], __float_as_uint(wa.z));
        PACKDUP(wd_[3], __float_as_uint(wa.w));
        PACKDUP(wd_[4], __float_as_uint(wb.x));
        PACKDUP(wd_[5], __float_as_uint(wb.y));
        PACKDUP(wd_[6], __float_as_uint(wb.z));
        PACKDUP(wd_[7], __float_as_uint(wb.w));
        #pragma unroll
        for (int p = 0; p < 4; ++p)
            #pragma unroll
            for (int g = 0; g < 8; ++g)
                FFMA2(acc[p][g], xp[p], wd_[g]);
    }

    // write partials: g_part[c][dim*64 + g]
    #pragma unroll
    for (int p = 0; p < 4; ++p) {
        #pragma unroll
        for (int k = 0; k < 2; ++k) {
            int dim = d0 + 8 * td + 2 * p + k;
            float4 v0, v1;
            unsigned long long a;
            a = acc[p][0]; v0.x = k ? __uint_as_float((unsigned)(a >> 32)) : __uint_as_float((unsigned)a);
            a = acc[p][1]; v0.y = k ? __uint_as_float((unsigned)(a >> 32)) : __uint_as_float((unsigned)a);
            a = acc[p][2]; v0.z = k ? __uint_as_float((unsigned)(a >> 32)) : __uint_as_float((unsigned)a);
            a = acc[p][3]; v0.w = k ? __uint_as_float((unsigned)(a >> 32)) : __uint_as_float((unsigned)a);
            a = acc[p][4]; v1.x = k ? __uint_as_float((unsigned)(a >> 32)) : __uint_as_float((unsigned)a);
            a = acc[p][5]; v1.y = k ? __uint_as_float((unsigned)(a >> 32)) : __uint_as_float((unsigned)a);
            a = acc[p][6]; v1.z = k ? __uint_as_float((unsigned)(a >> 32)) : __uint_as_float((unsigned)a);
            a = acc[p][7]; v1.w = k ? __uint_as_float((unsigned)(a >> 32)) : __uint_as_float((unsigned)a);
            float* dst = &g_part[c * (HIDDEN * N_GRAPHS) + dim * 64 + 8 * tg];
            *(float4*)dst = v0;
            *(float4*)(dst + 4) = v1;
        }
    }
}

// blocks 0..127: reduce partials into q[g][d]; blocks 128..191: d1/cnt per graph
__global__ void __launch_bounds__(256) k_qred_d1() {
    if (blockIdx.x < 128) {
        int o = blockIdx.x * 256 + threadIdx.x;    // 0..32767
        int dim = o >> 6, g = o & 63;
        float s = 0.f;
        #pragma unroll 5
        for (int c = 0; c < NCHUNK; ++c)
            s += g_part[c * (HIDDEN * N_GRAPHS) + o];
        g_q[g * HIDDEN + dim] = s;
    } else {
        __shared__ float red[256];
        int g = blockIdx.x - 128;
        if (g >= N_GRAPHS) return;
        int beg = g_gstart[g], end = g_gstart[g + 1];
        float s = 0.f;
        for (int i = beg + threadIdx.x; i < end; i += 256)
            s += 1.f + (float)g_indeg[i];
        red[threadIdx.x] = s;
        __syncthreads();
        for (int st = 128; st > 0; st >>= 1) {
            if (threadIdx.x < st) red[threadIdx.x] += red[threadIdx.x + st];
            __syncthreads();
        }
        if (threadIdx.x == 0) {
            g_d1[g]  = red[0];
            g_cnt[g] = (float)(end - beg);
        }
    }
}

// out[g][j] = sum_k in[g][k]*W[k][j] + scale[g]*bias[j]
// grid 64 (j-tiles of 8), block 256: thread handles (g = t&63, j = j0+2*(t>>6)+{0,1})
__global__ void __launch_bounds__(256) k_lin(const float* __restrict__ in,
                                             const float* __restrict__ W,
                                             const float* __restrict__ bias,
                                             const float* __restrict__ scale,
                                             float* __restrict__ out) {
    __shared__ float qs[64 * 65];
    int t = threadIdx.x;
    int g = t & 63;
    int j0 = blockIdx.x * 8 + 2 * (t >> 6);
    float a0 = 0.f, a1 = 0.f;
    for (int kc = 0; kc < HIDDEN; kc += 64) {
        #pragma unroll
        for (int it = 0; it < 16; ++it) {
            int f = it * 256 + t;
            int g2 = f >> 6, kk = f & 63;
            qs[g2 * 65 + kk] = in[g2 * HIDDEN + kc + kk];
        }
        __syncthreads();
        #pragma unroll 8
        for (int kk = 0; kk < 64; ++kk) {
            float qv = qs[g * 65 + kk];
            float2 w = *(const float2*)&W[(kc + kk) * HIDDEN + j0];
            a0 += qv * w.x;
            a1 += qv * w.y;
        }
        __syncthreads();
    }
    float sc = scale[g];
    out[g * HIDDEN + j0]     = a0 + sc * bias[j0];
    out[g * HIDDEN + j0 + 1] = a1 + sc * bias[j0 + 1];
}

// classifier head: per graph — zc = relu(pooled@Wc1 + bc1); score = zc@Wc2 + bc2; sigmoid
__global__ void __launch_bounds__(256) k_score(const float* __restrict__ Wc1,
                                               const float* __restrict__ bc1,
                                               const float* __restrict__ Wc2,
                                               const float* __restrict__ bc2,
                                               float* __restrict__ out) {
    __shared__ float ps[HIDDEN];
    __shared__ float red[256];
    int g = blockIdx.x, t = threadIdx.x;
    ps[t]       = g_pooled[g * HIDDEN + t];
    ps[t + 256] = g_pooled[g * HIDDEN + t + 256];
    __syncthreads();
    float acc = 0.f;
    #pragma unroll 8
    for (int k = 0; k < HIDDEN; ++k)
        acc += ps[k] * Wc1[k * HALF_H + t];
    float z = acc + bc1[t];
    z = z > 0.f ? z : 0.f;
    red[t] = z * Wc2[t];
    __syncthreads();
    for (int s = 128; s > 0; s >>= 1) {
        if (t < s) red[t] += red[t + s];
        __syncthreads();
    }
    if (t == 0) {
        float sc = red[0] + bc2[0];
        out[g] = 1.f / (1.f + expf(-sc));
    }
}

// ---------------- host launch ----------------
extern "C" void kernel_launch(void* const* d_in, const int* in_sizes, int n_in,
                              void* d_out, int out_size) {
    const float* x     = (const float*)d_in[0];
    const int*   eidx  = (const int*)  d_in[1];
    const int*   batch = (const int*)  d_in[2];
    const float* W_g1  = (const float*)d_in[3];
    const float* b_g1  = (const float*)d_in[4];
    const float* W_g2  = (const float*)d_in[5];
    const float* b_g2  = (const float*)d_in[6];
    const float* W_c1  = (const float*)d_in[7];
    const float* b_c1  = (const float*)d_in[8];
    const float* W_c2  = (const float*)d_in[9];
    const float* b_c2  = (const float*)d_in[10];
    float* out = (float*)d_out;

    const int* src = eidx;
    const int* dst = eidx + N_EDGES;

    float *q_ptr, *d1_ptr, *cnt_ptr, *t_ptr, *pooled_ptr;
    cudaGetSymbolAddress((void**)&q_ptr,     g_q);
    cudaGetSymbolAddress((void**)&d1_ptr,    g_d1);
    cudaGetSymbolAddress((void**)&cnt_ptr,   g_cnt);
    cudaGetSymbolAddress((void**)&t_ptr,     g_t);
    cudaGetSymbolAddress((void**)&pooled_ptr,g_pooled);

    k_init<<<(N_NODES + 255) / 256, 256>>>(batch);
    k_hist<<<N_EDGES / 512, 512>>>(src, dst);
    k_scan<<<1, 1024>>>();
    k_scatter<<<N_EDGES / 512, 512>>>(src, dst);
    k_w1<<<(N_NODES + 7) / 8, 256>>>(batch);
    k_w2<<<(N_NODES + 7) / 8, 256>>>();
    k_qgemm<<<dim3(NCHUNK, 2), 256>>>(x);
    k_qred_d1<<<192, 256>>>();
    k_lin<<<64, 256>>>(q_ptr, W_g1, b_g1, d1_ptr, t_ptr);
    k_lin<<<64, 256>>>(t_ptr, W_g2, b_g2, cnt_ptr, pooled_ptr);
    k_score<<<64, 256>>>(W_c1, b_c1, W_c2, b_c2, out);
}